// round 4
// baseline (speedup 1.0000x reference)
#include <cuda_runtime.h>

#define NMAX 100000
#define EMAX 1600000
#define DV 128

// Scratch (device globals — allocation-free per harness rules)
__device__ float g_H[NMAX * DV];      // node features (post-layer)
__device__ float g_M[NMAX * DV];      // messages: (h @ W) * dinv[row]
__device__ float g_dinv[NMAX];
__device__ int   g_deg[NMAX];
__device__ int   g_cur[NMAX];
__device__ int   g_rptr[NMAX + 1];
__device__ int   g_col[EMAX];
__device__ int   g_src[EMAX];
__device__ int   g_dst[EMAX];
__device__ int   g_batch[NMAX];
__device__ int   g_is64;

// ---------------- dtype probe: int64 vs int32 index buffers ----------------
__global__ void k_detect(const void* edge, int E) {
    const long long* e64 = (const long long*)edge;
    int ok = 1;
    for (int i = 0; i < 8; i++) {
        long long v = e64[i];
        if (v < 0 || v >= (1LL << 31)) ok = 0;
    }
    g_is64 = ok;
}

// ---------------- normalize edge + batch to int32 ----------------
__global__ void k_cvt_edge(const void* edge, int E) {
    int i = blockIdx.x * blockDim.x + threadIdx.x;
    if (i >= E) return;
    int s, d;
    if (g_is64) {
        const long long* e = (const long long*)edge;
        s = (int)e[i];
        d = (int)e[E + i];
    } else {
        const int* e = (const int*)edge;
        s = e[i];
        d = e[E + i];
    }
    g_src[i] = s;
    g_dst[i] = d;
}

__global__ void k_cvt_batch(const void* batch, int N) {
    int i = blockIdx.x * blockDim.x + threadIdx.x;
    if (i >= N) return;
    g_batch[i] = g_is64 ? (int)((const long long*)batch)[i]
                        : ((const int*)batch)[i];
}

// ---------------- zero counters ----------------
__global__ void k_zero(int N) {
    int i = blockIdx.x * blockDim.x + threadIdx.x;
    if (i < N) { g_deg[i] = 0; g_cur[i] = 0; }
}

// ---------------- degree histogram on dst (clamped: trap-proof) ----------------
__global__ void k_deg(int E, int N) {
    int i = blockIdx.x * blockDim.x + threadIdx.x;
    if (i >= E) return;
    unsigned d = (unsigned)g_dst[i];
    if (d < (unsigned)N) atomicAdd(&g_deg[d], 1);
}

__global__ void k_dinv(int N) {
    int i = blockIdx.x * blockDim.x + threadIdx.x;
    if (i < N) g_dinv[i] = rsqrtf((float)(g_deg[i] + 1));   // +1 self-loop
}

// ---------------- exclusive scan -> g_rptr (single block, 1024 thr) ----------------
__global__ void __launch_bounds__(1024) k_scan(int N) {
    __shared__ int ssum[1024];
    int t = threadIdx.x;
    int per = (N + 1023) / 1024;
    int begin = t * per;
    int end   = begin + per; if (end > N) end = N; if (begin > N) begin = N;
    int s = 0;
    for (int i = begin; i < end; i++) s += g_deg[i];
    ssum[t] = s;
    __syncthreads();
    for (int off = 1; off < 1024; off <<= 1) {
        int v = (t >= off) ? ssum[t - off] : 0;
        __syncthreads();
        ssum[t] += v;
        __syncthreads();
    }
    int run = (t == 0) ? 0 : ssum[t - 1];
    for (int i = begin; i < end; i++) { g_rptr[i] = run; run += g_deg[i]; }
    if (t == 1023) g_rptr[N] = run;
}

// ---------------- CSR fill: bucket src indices by dst (clamped) ----------------
__global__ void k_fill(int E, int N) {
    int i = blockIdx.x * blockDim.x + threadIdx.x;
    if (i >= E) return;
    unsigned d = (unsigned)g_dst[i];
    unsigned s = (unsigned)g_src[i];
    if (d >= (unsigned)N || s >= (unsigned)N) return;
    int pos = atomicAdd(&g_cur[d], 1);
    g_col[g_rptr[d] + pos] = (int)s;
}

// ---------------- GEMM: M = (Hin @ W) * dinv[row]  (intrinsics only) ----------------
__global__ void __launch_bounds__(256) k_gemm(const float* __restrict__ xin,
                                              const float* __restrict__ W,
                                              int N, int useH) {
    const float* __restrict__ Hin = useH ? (const float*)g_H : xin;
    __shared__ float Ws[64][128];   // 32 KB
    __shared__ float Hs[64][64];    // 16 KB

    int tid  = threadIdx.x;
    int row0 = blockIdx.x * 64;
    int tx   = tid & 15;   // 16 col-groups of 8 output cols
    int ty   = tid >> 4;   // 16 row-groups of 4 rows

    float acc[4][8];
#pragma unroll
    for (int r = 0; r < 4; r++)
#pragma unroll
        for (int c = 0; c < 8; c++) acc[r][c] = 0.f;

    for (int kk = 0; kk < 128; kk += 64) {
        __syncthreads();
        const float4* W4  = (const float4*)(W + (size_t)kk * 128);
        float4*       Ws4 = (float4*)&Ws[0][0];
#pragma unroll
        for (int i = 0; i < 8; i++) Ws4[tid + i * 256] = W4[tid + i * 256];
#pragma unroll
        for (int i = 0; i < 4; i++) {
            int j   = tid + i * 256;
            int row = j >> 4;
            int c4  = j & 15;
            float4 v = make_float4(0.f, 0.f, 0.f, 0.f);
            if (row0 + row < N)
                v = ((const float4*)(Hin + (size_t)(row0 + row) * 128 + kk))[c4];
            ((float4*)&Hs[row][0])[c4] = v;
        }
        __syncthreads();

#pragma unroll 4
        for (int k = 0; k < 64; k++) {
            float4 w0 = *(const float4*)&Ws[k][tx * 8];
            float4 w1 = *(const float4*)&Ws[k][tx * 8 + 4];
#pragma unroll
            for (int r = 0; r < 4; r++) {
                float a = Hs[ty * 4 + r][k];
                acc[r][0] = fmaf(a, w0.x, acc[r][0]);
                acc[r][1] = fmaf(a, w0.y, acc[r][1]);
                acc[r][2] = fmaf(a, w0.z, acc[r][2]);
                acc[r][3] = fmaf(a, w0.w, acc[r][3]);
                acc[r][4] = fmaf(a, w1.x, acc[r][4]);
                acc[r][5] = fmaf(a, w1.y, acc[r][5]);
                acc[r][6] = fmaf(a, w1.z, acc[r][6]);
                acc[r][7] = fmaf(a, w1.w, acc[r][7]);
            }
        }
    }

#pragma unroll
    for (int r = 0; r < 4; r++) {
        int row = row0 + ty * 4 + r;
        if (row >= N) continue;
        float dv = g_dinv[row];
        float4* Mp = (float4*)(g_M + (size_t)row * 128 + tx * 8);
        Mp[0] = make_float4(acc[r][0] * dv, acc[r][1] * dv, acc[r][2] * dv, acc[r][3] * dv);
        Mp[1] = make_float4(acc[r][4] * dv, acc[r][5] * dv, acc[r][6] * dv, acc[r][7] * dv);
    }
}

// ---------------- gather aggregation + bias + relu ----------------
// H[d] = relu( dinv[d] * ( M[d] + sum_{e: dst=d} M[src_e] ) + b )
__global__ void __launch_bounds__(256) k_gather(const float* __restrict__ b, int N) {
    int w = (blockIdx.x * 256 + threadIdx.x) >> 5;
    if (w >= N) return;
    int lane = threadIdx.x & 31;

    int s0 = g_rptr[w], s1 = g_rptr[w + 1];
    float dv = g_dinv[w];
    const float4* M4 = (const float4*)g_M;

    float4 acc = M4[(size_t)w * 32 + lane];   // self-loop message (pre-scaled by dinv[w])

    int e = s0;
    for (; e + 3 < s1; e += 4) {
        int sa = g_col[e], sb = g_col[e + 1], sc = g_col[e + 2], sd = g_col[e + 3];
        float4 va = M4[(size_t)sa * 32 + lane];
        float4 vb = M4[(size_t)sb * 32 + lane];
        float4 vc = M4[(size_t)sc * 32 + lane];
        float4 vd = M4[(size_t)sd * 32 + lane];
        acc.x += va.x + vb.x + vc.x + vd.x;
        acc.y += va.y + vb.y + vc.y + vd.y;
        acc.z += va.z + vb.z + vc.z + vd.z;
        acc.w += va.w + vb.w + vc.w + vd.w;
    }
    for (; e < s1; e++) {
        int s = g_col[e];
        float4 v = M4[(size_t)s * 32 + lane];
        acc.x += v.x; acc.y += v.y; acc.z += v.z; acc.w += v.w;
    }

    float4 bb = ((const float4*)b)[lane];
    float4 o;
    o.x = fmaxf(acc.x * dv + bb.x, 0.f);
    o.y = fmaxf(acc.y * dv + bb.y, 0.f);
    o.z = fmaxf(acc.z * dv + bb.z, 0.f);
    o.w = fmaxf(acc.w * dv + bb.w, 0.f);
    ((float4*)g_H)[(size_t)w * 32 + lane] = o;
}

// ---------------- fused pooling (max/mean/sum) + output linear (no atomics) ----------------
__global__ void __launch_bounds__(128) k_pool_out(const float* __restrict__ out_w,
                                                  const float* __restrict__ out_b,
                                                  float* __restrict__ out, int N) {
    int g = blockIdx.x;    // 256 graphs
    int d = threadIdx.x;   // 128 dims

    // g_batch is sorted: binary search segment [lo, hi)
    int lo, hi;
    { int a = 0, b = N; while (a < b) { int m = (a + b) >> 1; if (g_batch[m] < g) a = m + 1; else b = m; } lo = a; }
    { int a = lo, b = N; while (a < b) { int m = (a + b) >> 1; if (g_batch[m] < g + 1) a = m + 1; else b = m; } hi = a; }

    float s = 0.f, mx = 0.f;   // relu output >= 0, so max init 0 matches segment_max for non-empty segments
    for (int n = lo; n < hi; n++) {
        float v = g_H[(size_t)n * 128 + d];
        s += v;
        mx = fmaxf(mx, v);
    }
    float cnt  = fmaxf((float)(hi - lo), 1.f);
    float mean = s / cnt;

    __shared__ float sp[128][10];
#pragma unroll
    for (int j = 0; j < 10; j++)
        sp[d][j] = mx * out_w[d * 10 + j]
                 + mean * out_w[(128 + d) * 10 + j]
                 + s * out_w[(256 + d) * 10 + j];
    __syncthreads();

    if (d < 10) {
        float r = 0.f;
        for (int i = 0; i < 128; i++) r += sp[i][d];
        out[g * 10 + d] = r + out_b[d];
    }
}

// ---------------- launch ----------------
extern "C" void kernel_launch(void* const* d_in, const int* in_sizes, int n_in,
                              void* d_out, int out_size) {
    const float* x      = (const float*)d_in[0];
    const void*  edge   = d_in[1];
    const void*  batch  = d_in[2];
    const float* conv_w = (const float*)d_in[3];
    const float* conv_b = (const float*)d_in[4];
    const float* out_w  = (const float*)d_in[5];
    const float* out_b  = (const float*)d_in[6];
    float*       out    = (float*)d_out;

    int N = in_sizes[0] / 128;
    int E = in_sizes[1] / 2;

    k_detect<<<1, 1>>>(edge, E);
    k_cvt_edge<<<(E + 255) / 256, 256>>>(edge, E);
    k_cvt_batch<<<(N + 255) / 256, 256>>>(batch, N);

    k_zero<<<(N + 255) / 256, 256>>>(N);
    k_deg<<<(E + 255) / 256, 256>>>(E, N);
    k_dinv<<<(N + 255) / 256, 256>>>(N);
    k_scan<<<1, 1024>>>(N);
    k_fill<<<(E + 255) / 256, 256>>>(E, N);

    for (int l = 0; l < 3; l++) {
        k_gemm<<<(N + 63) / 64, 256>>>(x, conv_w + (size_t)l * 128 * 128, N, l > 0 ? 1 : 0);
        k_gather<<<(N * 32 + 255) / 256, 256>>>(conv_b + l * 128, N);
    }

    k_pool_out<<<256, 128>>>(out_w, out_b, out, N);
}